// round 1
// baseline (speedup 1.0000x reference)
#include <cuda_runtime.h>
#include <math.h>
#include <float.h>

// AUAvULoss: N=65536 rows, C=1000 classes fp32 logits, int64 labels.
// K1: per-row softmax stats (one block per row)  -> g_unc / g_confacc / g_ce
// K2: global min/max of unc + CE sum             -> g_umin_bits/g_umax_bits/g_cesum
// K3: cutoff-index histogram into 88 bins        -> g_bins
// K4: prefix/suffix sums -> avu[21] -> trapezoid -> loss scalar

#define MAXN 65536

__device__ float g_unc[MAXN];
__device__ float g_confacc[MAXN];   // +conf if accurate, -conf if not
__device__ float g_ce[MAXN];
__device__ unsigned int g_umin_bits;
__device__ unsigned int g_umax_bits;
__device__ float g_cesum;
// layout: [acc(0/1)][kind(0=certain-weight,1=uncertain-weight)][j0 in 0..21]
__device__ float g_bins[88];

__device__ __forceinline__ unsigned int f2ord(float f) {
    unsigned int u = __float_as_uint(f);
    return (u & 0x80000000u) ? ~u : (u | 0x80000000u);
}
__device__ __forceinline__ float ord2f(unsigned int u) {
    return __uint_as_float((u & 0x80000000u) ? (u ^ 0x80000000u) : ~u);
}

__global__ void k_init() {
    int t = threadIdx.x;
    if (t < 88) g_bins[t] = 0.0f;
    if (t == 0) {
        g_umin_bits = 0xFFFFFFFFu;
        g_umax_bits = 0u;
        g_cesum = 0.0f;
    }
}

// ---------------- K1: one block per row ----------------
template <int BLK>
__global__ void __launch_bounds__(BLK)
k_rows(const float* __restrict__ logits,
       const long long* __restrict__ labels,
       int C) {
    const int row  = blockIdx.x;
    const int tid  = threadIdx.x;
    const int lane = tid & 31;
    const int wid  = tid >> 5;
    const int chunks = C >> 2;                 // C % 4 == 0
    const float4* __restrict__ rp =
        reinterpret_cast<const float4*>(logits + (size_t)row * (size_t)C);

    // ---- load row into registers, local max + first-index argmax ----
    float4 buf[4];
    int nloc = 0;
    float m = -FLT_MAX;
    int mi = 0x7FFFFFFF;
    for (int c = tid; c < chunks; c += BLK) {
        float4 v = rp[c];
        buf[nloc++] = v;
        int base = c << 2;
        if (v.x > m) { m = v.x; mi = base; }
        if (v.y > m) { m = v.y; mi = base + 1; }
        if (v.z > m) { m = v.z; mi = base + 2; }
        if (v.w > m) { m = v.w; mi = base + 3; }
    }

    __shared__ float s_f[BLK / 32];
    __shared__ int   s_ix[BLK / 32];
    __shared__ float s_S[BLK / 32];
    __shared__ float s_T[BLK / 32];

    // warp reduce (max, first idx)
    #pragma unroll
    for (int o = 16; o > 0; o >>= 1) {
        float om = __shfl_down_sync(0xffffffffu, m, o);
        int   oi = __shfl_down_sync(0xffffffffu, mi, o);
        if (om > m || (om == m && oi < mi)) { m = om; mi = oi; }
    }
    if (lane == 0) { s_f[wid] = m; s_ix[wid] = mi; }
    __syncthreads();
    if (wid == 0) {
        m  = (lane < BLK / 32) ? s_f[lane]  : -FLT_MAX;
        mi = (lane < BLK / 32) ? s_ix[lane] : 0x7FFFFFFF;
        #pragma unroll
        for (int o = (BLK / 64); o > 0; o >>= 1) {
            float om = __shfl_down_sync(0xffffffffu, m, o);
            int   oi = __shfl_down_sync(0xffffffffu, mi, o);
            if (om > m || (om == m && oi < mi)) { m = om; mi = oi; }
        }
        if (lane == 0) { s_f[0] = m; s_ix[0] = mi; }
    }
    __syncthreads();
    const float rm = s_f[0];

    // ---- pass 2 over registers: S = sum e^d, T = sum d*e^d ----
    float S = 0.0f, T = 0.0f;
    for (int k = 0; k < nloc; k++) {
        float4 v = buf[k];
        float d, e;
        d = v.x - rm; e = __expf(d); S += e; T = fmaf(d, e, T);
        d = v.y - rm; e = __expf(d); S += e; T = fmaf(d, e, T);
        d = v.z - rm; e = __expf(d); S += e; T = fmaf(d, e, T);
        d = v.w - rm; e = __expf(d); S += e; T = fmaf(d, e, T);
    }
    #pragma unroll
    for (int o = 16; o > 0; o >>= 1) {
        S += __shfl_down_sync(0xffffffffu, S, o);
        T += __shfl_down_sync(0xffffffffu, T, o);
    }
    if (lane == 0) { s_S[wid] = S; s_T[wid] = T; }
    __syncthreads();

    if (tid == 0) {
        float Ss = 0.0f, Ts = 0.0f;
        #pragma unroll
        for (int w = 0; w < BLK / 32; w++) { Ss += s_S[w]; Ts += s_T[w]; }
        float conf = 1.0f / Ss;                 // max prob = e^0 / S
        float logS = logf(Ss);
        float unc  = logS - Ts / Ss;            // -sum p log p
        int lbl = (int)labels[row];
        float zl = logits[(size_t)row * (size_t)C + lbl];
        float ce = (rm - zl) + logS;            // -log_softmax at label
        int pred = s_ix[0];
        g_unc[row]     = unc;
        g_confacc[row] = (pred == lbl) ? conf : -conf;
        g_ce[row]      = ce;
    }
}

// ---------------- K2: min/max of unc + CE sum ----------------
template <int BLK>
__global__ void __launch_bounds__(BLK)
k_minmax_ce(int n) {
    const int tid  = threadIdx.x;
    const int lane = tid & 31;
    const int wid  = tid >> 5;
    float mn = FLT_MAX, mx = -FLT_MAX, cs = 0.0f;
    for (int i = blockIdx.x * BLK + tid; i < n; i += gridDim.x * BLK) {
        float u = g_unc[i];
        mn = fminf(mn, u);
        mx = fmaxf(mx, u);
        cs += g_ce[i];
    }
    #pragma unroll
    for (int o = 16; o > 0; o >>= 1) {
        mn = fminf(mn, __shfl_down_sync(0xffffffffu, mn, o));
        mx = fmaxf(mx, __shfl_down_sync(0xffffffffu, mx, o));
        cs += __shfl_down_sync(0xffffffffu, cs, o);
    }
    __shared__ float sm[BLK / 32], sx[BLK / 32], sc[BLK / 32];
    if (lane == 0) { sm[wid] = mn; sx[wid] = mx; sc[wid] = cs; }
    __syncthreads();
    if (tid == 0) {
        for (int w = 1; w < BLK / 32; w++) {
            mn = fminf(mn, sm[w]);
            mx = fmaxf(mx, sx[w]);
            cs += sc[w];
        }
        atomicMin(&g_umin_bits, f2ord(mn));
        atomicMax(&g_umax_bits, f2ord(mx));
        atomicAdd(&g_cesum, cs);
    }
}

// ---------------- K3: cutoff histogram ----------------
template <int BLK>
__global__ void __launch_bounds__(BLK)
k_bins(int n) {
    __shared__ float sb[88];
    if (threadIdx.x < 88) sb[threadIdx.x] = 0.0f;
    __syncthreads();

    const float umin  = ord2f(g_umin_bits);
    const float umax  = ord2f(g_umax_bits);
    const float range = umax - umin;

    for (int i = blockIdx.x * BLK + threadIdx.x; i < n; i += gridDim.x * BLK) {
        float unc = g_unc[i];
        float ca  = g_confacc[i];
        int acc   = (ca > 0.0f) ? 1 : 0;
        float conf = fabsf(ca);
        float w = acc ? conf : (1.0f - conf);
        float t = tanhf(unc);
        float bc = w * (1.0f - t);   // contribution if certain
        float bu = w * t;            // contribution if uncertain
        int j0 = 21;                 // smallest j with unc <= th_j (21 = never)
        #pragma unroll
        for (int j = 20; j >= 0; j--) {
            float thv = umin + (0.05f * (float)j) * range;
            if (unc <= thv) j0 = j;
        }
        atomicAdd(&sb[acc * 44 + j0], bc);
        atomicAdd(&sb[acc * 44 + 22 + j0], bu);
    }
    __syncthreads();
    if (threadIdx.x < 88) atomicAdd(&g_bins[threadIdx.x], sb[threadIdx.x]);
}

// ---------------- K4: final scalar ----------------
__global__ void k_final(float* __restrict__ out, int n) {
    // suffix totals for the "uncertain" weights
    float au_rem = 0.0f, iu_rem = 0.0f;
    for (int k = 0; k < 22; k++) {
        au_rem += g_bins[66 + k];   // acc=1, kind=U
        iu_rem += g_bins[22 + k];   // acc=0, kind=U
    }
    float nac = 0.0f, nic = 0.0f;
    float avu[21];
    for (int j = 0; j < 21; j++) {
        nac    += g_bins[44 + j];   // acc=1, kind=C prefix
        nic    += g_bins[j];        // acc=0, kind=C prefix
        au_rem -= g_bins[66 + j];   // now sum over j0 > j
        iu_rem -= g_bins[22 + j];
        avu[j] = (nac + iu_rem) / (nac + au_rem + nic + iu_rem + 1e-12f);
    }
    float auc = 0.0f;
    for (int j = 0; j < 20; j++) auc += (avu[j + 1] + avu[j]);
    auc *= 0.5f * 0.05f;
    out[0] = -3.0f * logf(auc + 1e-12f) + g_cesum / (float)n;
}

extern "C" void kernel_launch(void* const* d_in, const int* in_sizes, int n_in,
                              void* d_out, int out_size) {
    const float*     logits = (const float*)d_in[0];
    const long long* labels = (const long long*)d_in[1];
    int n = in_sizes[1];
    int C = in_sizes[0] / n;

    k_init<<<1, 128>>>();
    k_rows<256><<<n, 256>>>(logits, labels, C);
    k_minmax_ce<256><<<64, 256>>>(n);
    k_bins<256><<<256, 256>>>(n);
    k_final<<<1, 1>>>((float*)d_out, n);
}

// round 2
// speedup vs baseline: 2.4392x; 2.4392x over previous
#include <cuda_runtime.h>
#include <math.h>
#include <float.h>

// AUAvULoss: N=65536 rows, C=1000 classes fp32 logits, int64 labels.
// K1: one WARP per row -> g_unc / g_confacc / g_ce   (registers + shfl only)
// K2: global min/max of unc + CE sum
// K3: cutoff-index histogram into 88 bins
// K4: prefix/suffix sums -> avu[21] -> trapezoid -> loss scalar

#define MAXN 65536

__device__ float g_unc[MAXN];
__device__ float g_confacc[MAXN];   // +conf if accurate, -conf if not
__device__ float g_ce[MAXN];
__device__ unsigned int g_umin_bits;
__device__ unsigned int g_umax_bits;
__device__ float g_cesum;
// layout: [acc(0/1)][kind(0=certain,1=uncertain)][j0 in 0..21]
__device__ float g_bins[88];

__device__ __forceinline__ unsigned int f2ord(float f) {
    unsigned int u = __float_as_uint(f);
    return (u & 0x80000000u) ? ~u : (u | 0x80000000u);
}
__device__ __forceinline__ float ord2f(unsigned int u) {
    return __uint_as_float((u & 0x80000000u) ? (u ^ 0x80000000u) : ~u);
}

__global__ void k_init() {
    int t = threadIdx.x;
    if (t < 88) g_bins[t] = 0.0f;
    if (t == 0) {
        g_umin_bits = 0xFFFFFFFFu;
        g_umax_bits = 0u;
        g_cesum = 0.0f;
    }
}

// ---------------- K1: one warp per row ----------------
// C <= 1024 assumed (C = 1000 here): 8 float4 chunks per lane max.
template <int WPB>   // warps per block
__global__ void __launch_bounds__(WPB * 32)
k_rows(const float* __restrict__ logits,
       const long long* __restrict__ labels,
       int C, int n) {
    const int warp = blockIdx.x * WPB + (threadIdx.x >> 5);
    if (warp >= n) return;
    const int row  = warp;
    const int lane = threadIdx.x & 31;
    const int chunks = (C + 3) >> 2;          // 250 for C=1000
    const float4* __restrict__ rp =
        reinterpret_cast<const float4*>(logits + (size_t)row * (size_t)C);

    // ---- front-batched loads: up to 8 float4 per lane ----
    float4 v[8];
    bool   ok[8];
    #pragma unroll
    for (int k = 0; k < 8; k++) {
        int c = lane + (k << 5);
        ok[k] = (c < chunks);
        if (ok[k]) v[k] = rp[c];
    }

    // ---- local max + first-index argmax ----
    float m = -FLT_MAX;
    int mi = 0x7FFFFFFF;
    #pragma unroll
    for (int k = 0; k < 8; k++) {
        if (ok[k]) {
            int base = (lane + (k << 5)) << 2;
            if (v[k].x > m) { m = v[k].x; mi = base; }
            if (v[k].y > m) { m = v[k].y; mi = base + 1; }
            if (v[k].z > m) { m = v[k].z; mi = base + 2; }
            if (v[k].w > m) { m = v[k].w; mi = base + 3; }
        }
    }
    // butterfly reduce (max, min index on tie) -> all lanes converge
    #pragma unroll
    for (int o = 16; o > 0; o >>= 1) {
        float om = __shfl_xor_sync(0xffffffffu, m, o);
        int   oi = __shfl_xor_sync(0xffffffffu, mi, o);
        if (om > m || (om == m && oi < mi)) { m = om; mi = oi; }
    }
    const float rm = m;
    const int pred = mi;

    // ---- S = sum e^d, T = sum d*e^d over registers ----
    float S = 0.0f, T = 0.0f;
    #pragma unroll
    for (int k = 0; k < 8; k++) {
        if (ok[k]) {
            float d, e;
            d = v[k].x - rm; e = __expf(d); S += e; T = fmaf(d, e, T);
            d = v[k].y - rm; e = __expf(d); S += e; T = fmaf(d, e, T);
            d = v[k].z - rm; e = __expf(d); S += e; T = fmaf(d, e, T);
            d = v[k].w - rm; e = __expf(d); S += e; T = fmaf(d, e, T);
        }
    }
    #pragma unroll
    for (int o = 16; o > 0; o >>= 1) {
        S += __shfl_xor_sync(0xffffffffu, S, o);
        T += __shfl_xor_sync(0xffffffffu, T, o);
    }

    if (lane == 0) {
        int lbl = (int)labels[row];
        float zl = __ldg(&logits[(size_t)row * (size_t)C + lbl]); // L1 hit
        float conf = 1.0f / S;                  // max prob = e^0 / S
        float logS = logf(S);
        float unc  = logS - T / S;              // entropy
        float ce   = (rm - zl) + logS;          // -log_softmax at label
        g_unc[row]     = unc;
        g_confacc[row] = (pred == lbl) ? conf : -conf;
        g_ce[row]      = ce;
    }
}

// ---------------- K2: min/max of unc + CE sum ----------------
template <int BLK>
__global__ void __launch_bounds__(BLK)
k_minmax_ce(int n) {
    const int tid  = threadIdx.x;
    const int lane = tid & 31;
    const int wid  = tid >> 5;
    float mn = FLT_MAX, mx = -FLT_MAX, cs = 0.0f;
    for (int i = blockIdx.x * BLK + tid; i < n; i += gridDim.x * BLK) {
        float u = g_unc[i];
        mn = fminf(mn, u);
        mx = fmaxf(mx, u);
        cs += g_ce[i];
    }
    #pragma unroll
    for (int o = 16; o > 0; o >>= 1) {
        mn = fminf(mn, __shfl_xor_sync(0xffffffffu, mn, o));
        mx = fmaxf(mx, __shfl_xor_sync(0xffffffffu, mx, o));
        cs += __shfl_xor_sync(0xffffffffu, cs, o);
    }
    __shared__ float sm[BLK / 32], sx[BLK / 32], sc[BLK / 32];
    if (lane == 0) { sm[wid] = mn; sx[wid] = mx; sc[wid] = cs; }
    __syncthreads();
    if (tid == 0) {
        for (int w = 1; w < BLK / 32; w++) {
            mn = fminf(mn, sm[w]);
            mx = fmaxf(mx, sx[w]);
            cs += sc[w];
        }
        atomicMin(&g_umin_bits, f2ord(mn));
        atomicMax(&g_umax_bits, f2ord(mx));
        atomicAdd(&g_cesum, cs);
    }
}

// ---------------- K3: cutoff histogram ----------------
template <int BLK>
__global__ void __launch_bounds__(BLK)
k_bins(int n) {
    __shared__ float sb[88];
    if (threadIdx.x < 88) sb[threadIdx.x] = 0.0f;
    __syncthreads();

    const float umin  = ord2f(g_umin_bits);
    const float umax  = ord2f(g_umax_bits);
    const float range = umax - umin;

    for (int i = blockIdx.x * BLK + threadIdx.x; i < n; i += gridDim.x * BLK) {
        float unc = g_unc[i];
        float ca  = g_confacc[i];
        int acc   = (ca > 0.0f) ? 1 : 0;
        float conf = fabsf(ca);
        float w = acc ? conf : (1.0f - conf);
        float t = tanhf(unc);
        float bc = w * (1.0f - t);   // contribution if certain
        float bu = w * t;            // contribution if uncertain
        int j0 = 21;                 // smallest j with unc <= th_j (21 = never)
        #pragma unroll
        for (int j = 20; j >= 0; j--) {
            float thv = umin + (0.05f * (float)j) * range;
            if (unc <= thv) j0 = j;
        }
        atomicAdd(&sb[acc * 44 + j0], bc);
        atomicAdd(&sb[acc * 44 + 22 + j0], bu);
    }
    __syncthreads();
    if (threadIdx.x < 88) atomicAdd(&g_bins[threadIdx.x], sb[threadIdx.x]);
}

// ---------------- K4: final scalar ----------------
__global__ void k_final(float* __restrict__ out, int n) {
    float au_rem = 0.0f, iu_rem = 0.0f;
    for (int k = 0; k < 22; k++) {
        au_rem += g_bins[66 + k];   // acc=1, kind=U
        iu_rem += g_bins[22 + k];   // acc=0, kind=U
    }
    float nac = 0.0f, nic = 0.0f;
    float avu[21];
    for (int j = 0; j < 21; j++) {
        nac    += g_bins[44 + j];   // acc=1, kind=C prefix
        nic    += g_bins[j];        // acc=0, kind=C prefix
        au_rem -= g_bins[66 + j];
        iu_rem -= g_bins[22 + j];
        avu[j] = (nac + iu_rem) / (nac + au_rem + nic + iu_rem + 1e-12f);
    }
    float auc = 0.0f;
    for (int j = 0; j < 20; j++) auc += (avu[j + 1] + avu[j]);
    auc *= 0.5f * 0.05f;
    out[0] = -3.0f * logf(auc + 1e-12f) + g_cesum / (float)n;
}

extern "C" void kernel_launch(void* const* d_in, const int* in_sizes, int n_in,
                              void* d_out, int out_size) {
    const float*     logits = (const float*)d_in[0];
    const long long* labels = (const long long*)d_in[1];
    int n = in_sizes[1];
    int C = in_sizes[0] / n;

    k_init<<<1, 128>>>();
    const int WPB = 8;                       // 256 threads, 8 rows per block
    k_rows<WPB><<<(n + WPB - 1) / WPB, WPB * 32>>>(logits, labels, C, n);
    k_minmax_ce<256><<<512, 256>>>(n);
    k_bins<256><<<1024, 256>>>(n);
    k_final<<<1, 1>>>((float*)d_out, n);
}

// round 3
// speedup vs baseline: 2.4540x; 1.0060x over previous
#include <cuda_runtime.h>
#include <math.h>
#include <float.h>

// AUAvULoss: N=65536 rows, C=1000 classes fp32 logits, int64 labels.
// K1: one WARP per row -> g_unc / g_confacc / g_ce   (registers + shfl only)
// K2: global min/max of unc + CE sum
// K3: cutoff-index histogram into 88 bins
// K4: prefix/suffix sums -> avu[21] -> trapezoid -> loss scalar

#define MAXN 65536

__device__ float g_unc[MAXN];
__device__ float g_confacc[MAXN];   // +conf if accurate, -conf if not
__device__ float g_ce[MAXN];
__device__ unsigned int g_umin_bits;
__device__ unsigned int g_umax_bits;
__device__ float g_cesum;
// layout: [acc(0/1)][kind(0=certain,1=uncertain)][j0 in 0..21]
__device__ float g_bins[88];

__device__ __forceinline__ unsigned int f2ord(float f) {
    unsigned int u = __float_as_uint(f);
    return (u & 0x80000000u) ? ~u : (u | 0x80000000u);
}
__device__ __forceinline__ float ord2f(unsigned int u) {
    return __uint_as_float((u & 0x80000000u) ? (u ^ 0x80000000u) : ~u);
}

__global__ void k_init() {
    int t = threadIdx.x;
    if (t < 88) g_bins[t] = 0.0f;
    if (t == 0) {
        g_umin_bits = 0xFFFFFFFFu;
        g_umax_bits = 0u;
        g_cesum = 0.0f;
    }
}

// ---------------- K1: one warp per row ----------------
// C <= 1024 assumed (C = 1000 here): 8 float4 chunks per lane max.
template <int WPB>   // warps per block
__global__ void __launch_bounds__(WPB * 32)
k_rows(const float* __restrict__ logits,
       const long long* __restrict__ labels,
       int C, int n) {
    const int warp = blockIdx.x * WPB + (threadIdx.x >> 5);
    if (warp >= n) return;
    const int row  = warp;
    const int lane = threadIdx.x & 31;
    const int chunks = (C + 3) >> 2;          // 250 for C=1000
    const float4* __restrict__ rp =
        reinterpret_cast<const float4*>(logits + (size_t)row * (size_t)C);

    // ---- front-batched loads: up to 8 float4 per lane ----
    float4 v[8];
    bool   ok[8];
    #pragma unroll
    for (int k = 0; k < 8; k++) {
        int c = lane + (k << 5);
        ok[k] = (c < chunks);
        if (ok[k]) v[k] = rp[c];
    }

    // ---- local max + first-index argmax ----
    float m = -FLT_MAX;
    int mi = 0x7FFFFFFF;
    #pragma unroll
    for (int k = 0; k < 8; k++) {
        if (ok[k]) {
            int base = (lane + (k << 5)) << 2;
            if (v[k].x > m) { m = v[k].x; mi = base; }
            if (v[k].y > m) { m = v[k].y; mi = base + 1; }
            if (v[k].z > m) { m = v[k].z; mi = base + 2; }
            if (v[k].w > m) { m = v[k].w; mi = base + 3; }
        }
    }
    // butterfly reduce (max, min index on tie) -> all lanes converge
    #pragma unroll
    for (int o = 16; o > 0; o >>= 1) {
        float om = __shfl_xor_sync(0xffffffffu, m, o);
        int   oi = __shfl_xor_sync(0xffffffffu, mi, o);
        if (om > m || (om == m && oi < mi)) { m = om; mi = oi; }
    }
    const float rm = m;
    const int pred = mi;

    // ---- S = sum e^d, T = sum d*e^d over registers ----
    float S = 0.0f, T = 0.0f;
    #pragma unroll
    for (int k = 0; k < 8; k++) {
        if (ok[k]) {
            float d, e;
            d = v[k].x - rm; e = __expf(d); S += e; T = fmaf(d, e, T);
            d = v[k].y - rm; e = __expf(d); S += e; T = fmaf(d, e, T);
            d = v[k].z - rm; e = __expf(d); S += e; T = fmaf(d, e, T);
            d = v[k].w - rm; e = __expf(d); S += e; T = fmaf(d, e, T);
        }
    }
    #pragma unroll
    for (int o = 16; o > 0; o >>= 1) {
        S += __shfl_xor_sync(0xffffffffu, S, o);
        T += __shfl_xor_sync(0xffffffffu, T, o);
    }

    if (lane == 0) {
        int lbl = (int)labels[row];
        float zl = __ldg(&logits[(size_t)row * (size_t)C + lbl]); // L1 hit
        float conf = 1.0f / S;                  // max prob = e^0 / S
        float logS = logf(S);
        float unc  = logS - T / S;              // entropy
        float ce   = (rm - zl) + logS;          // -log_softmax at label
        g_unc[row]     = unc;
        g_confacc[row] = (pred == lbl) ? conf : -conf;
        g_ce[row]      = ce;
    }
}

// ---------------- K2: min/max of unc + CE sum ----------------
template <int BLK>
__global__ void __launch_bounds__(BLK)
k_minmax_ce(int n) {
    const int tid  = threadIdx.x;
    const int lane = tid & 31;
    const int wid  = tid >> 5;
    float mn = FLT_MAX, mx = -FLT_MAX, cs = 0.0f;
    for (int i = blockIdx.x * BLK + tid; i < n; i += gridDim.x * BLK) {
        float u = g_unc[i];
        mn = fminf(mn, u);
        mx = fmaxf(mx, u);
        cs += g_ce[i];
    }
    #pragma unroll
    for (int o = 16; o > 0; o >>= 1) {
        mn = fminf(mn, __shfl_xor_sync(0xffffffffu, mn, o));
        mx = fmaxf(mx, __shfl_xor_sync(0xffffffffu, mx, o));
        cs += __shfl_xor_sync(0xffffffffu, cs, o);
    }
    __shared__ float sm[BLK / 32], sx[BLK / 32], sc[BLK / 32];
    if (lane == 0) { sm[wid] = mn; sx[wid] = mx; sc[wid] = cs; }
    __syncthreads();
    if (tid == 0) {
        for (int w = 1; w < BLK / 32; w++) {
            mn = fminf(mn, sm[w]);
            mx = fmaxf(mx, sx[w]);
            cs += sc[w];
        }
        atomicMin(&g_umin_bits, f2ord(mn));
        atomicMax(&g_umax_bits, f2ord(mx));
        atomicAdd(&g_cesum, cs);
    }
}

// ---------------- K3: cutoff histogram ----------------
template <int BLK>
__global__ void __launch_bounds__(BLK)
k_bins(int n) {
    __shared__ float sb[88];
    if (threadIdx.x < 88) sb[threadIdx.x] = 0.0f;
    __syncthreads();

    const float umin  = ord2f(g_umin_bits);
    const float umax  = ord2f(g_umax_bits);
    const float range = umax - umin;

    for (int i = blockIdx.x * BLK + threadIdx.x; i < n; i += gridDim.x * BLK) {
        float unc = g_unc[i];
        float ca  = g_confacc[i];
        int acc   = (ca > 0.0f) ? 1 : 0;
        float conf = fabsf(ca);
        float w = acc ? conf : (1.0f - conf);
        float t = tanhf(unc);
        float bc = w * (1.0f - t);   // contribution if certain
        float bu = w * t;            // contribution if uncertain
        int j0 = 21;                 // smallest j with unc <= th_j (21 = never)
        #pragma unroll
        for (int j = 20; j >= 0; j--) {
            float thv = umin + (0.05f * (float)j) * range;
            if (unc <= thv) j0 = j;
        }
        atomicAdd(&sb[acc * 44 + j0], bc);
        atomicAdd(&sb[acc * 44 + 22 + j0], bu);
    }
    __syncthreads();
    if (threadIdx.x < 88) atomicAdd(&g_bins[threadIdx.x], sb[threadIdx.x]);
}

// ---------------- K4: final scalar ----------------
__global__ void k_final(float* __restrict__ out, int n) {
    float au_rem = 0.0f, iu_rem = 0.0f;
    for (int k = 0; k < 22; k++) {
        au_rem += g_bins[66 + k];   // acc=1, kind=U
        iu_rem += g_bins[22 + k];   // acc=0, kind=U
    }
    float nac = 0.0f, nic = 0.0f;
    float avu[21];
    for (int j = 0; j < 21; j++) {
        nac    += g_bins[44 + j];   // acc=1, kind=C prefix
        nic    += g_bins[j];        // acc=0, kind=C prefix
        au_rem -= g_bins[66 + j];
        iu_rem -= g_bins[22 + j];
        avu[j] = (nac + iu_rem) / (nac + au_rem + nic + iu_rem + 1e-12f);
    }
    float auc = 0.0f;
    for (int j = 0; j < 20; j++) auc += (avu[j + 1] + avu[j]);
    auc *= 0.5f * 0.05f;
    out[0] = -3.0f * logf(auc + 1e-12f) + g_cesum / (float)n;
}

extern "C" void kernel_launch(void* const* d_in, const int* in_sizes, int n_in,
                              void* d_out, int out_size) {
    const float*     logits = (const float*)d_in[0];
    const long long* labels = (const long long*)d_in[1];
    int n = in_sizes[1];
    int C = in_sizes[0] / n;

    k_init<<<1, 128>>>();
    const int WPB = 8;                       // 256 threads, 8 rows per block
    k_rows<WPB><<<(n + WPB - 1) / WPB, WPB * 32>>>(logits, labels, C, n);
    k_minmax_ce<256><<<512, 256>>>(n);
    k_bins<256><<<1024, 256>>>(n);
    k_final<<<1, 1>>>((float*)d_out, n);
}